// round 13
// baseline (speedup 1.0000x reference)
#include <cuda_runtime.h>
#include <cuda_fp16.h>
#include <cstdint>

// ---------------- problem constants ----------------
#define B_    16
#define CIN   512
#define COUT  256
#define H_    56
#define W_    56
#define HO    28
#define WO    28
#define NPB   784
#define NTOT  (B_ * NPB)          // 12544
#define HW    (H_ * W_)
#define NBLK  (NTOT / 64)         // 196

// grid roles (consumers FIRST for overlap; producers after)
#define NCON  392                 // gemm consumer CTAs (2 mblk x 196 nblk)
#define NWB   32                  // W-prep blocks
#define NPOOL 1568                // pool blocks (8 chunks x 196 nblk), chunk-major
#define GRID  (NCON + NWB + NPOOL)

// scratch (pre-swizzled; g_yh is k-major per 64x64 tile)
__device__ __align__(1024) __half g_wh[8 * 2 * 128 * 64];
__device__ __align__(1024) __half g_yh[(size_t)8 * NBLK * 64 * 64];
__device__ int g_flag[8 * NBLK];
__device__ int g_wflag;

__device__ __forceinline__ uint32_t smem_u32(const void* p) {
    uint32_t a;
    asm("{ .reg .u64 t; cvta.to.shared.u64 t, %1; cvt.u32.u64 %0, t; }" : "=r"(a) : "l"(p));
    return a;
}
__device__ __forceinline__ int ld_acq(const int* p) {
    int v;
    asm volatile("ld.acquire.gpu.global.b32 %0, [%1];" : "=r"(v) : "l"(p) : "memory");
    return v;
}
__device__ __forceinline__ void set_flag(int* p) {
    asm volatile("fence.acq_rel.gpu;" ::: "memory");
    atomicExch(p, 1);
}
#define FENCE_PROXY() asm volatile("fence.proxy.async;" ::: "memory")
#define MBAR_INIT(a, c) \
    asm volatile("mbarrier.init.shared.b64 [%0], %1;" :: "r"(a), "r"(c) : "memory")
#define MBAR_EXPECT_TX(a, b) \
    asm volatile("mbarrier.arrive.expect_tx.shared.b64 _, [%0], %1;" :: "r"(a), "r"(b) : "memory")
__device__ __forceinline__ void mbar_wait(uint32_t a, uint32_t parity) {
    asm volatile(
        "{\n\t.reg .pred P;\n\t"
        "W_%=:\n\t"
        "mbarrier.try_wait.parity.acquire.cta.shared::cta.b64 P, [%0], %1, 0x989680;\n\t"
        "@P bra.uni D_%=;\n\t"
        "bra.uni W_%=;\n\t"
        "D_%=:\n\t}"
        :: "r"(a), "r"(parity) : "memory");
}
#define BULK_G2S(dst, src, bytes, mbar) \
    asm volatile("cp.async.bulk.shared::cluster.global.mbarrier::complete_tx::bytes " \
                 "[%0], [%1], %2, [%3];" \
                 :: "r"(dst), "l"(src), "r"(bytes), "r"(mbar) : "memory")
#define LDSM4(R0, R1, R2, R3, A) \
    asm volatile("ldmatrix.sync.aligned.m8n8.x4.shared.b16 {%0,%1,%2,%3}, [%4];" \
                 : "=r"(R0), "=r"(R1), "=r"(R2), "=r"(R3) : "r"(A))
#define LDSM4T(R0, R1, R2, R3, A) \
    asm volatile("ldmatrix.sync.aligned.m8n8.x4.trans.shared.b16 {%0,%1,%2,%3}, [%4];" \
                 : "=r"(R0), "=r"(R1), "=r"(R2), "=r"(R3) : "r"(A))
#define MMAF16(C, A0, A1, A2, A3, B0, B1) \
    asm volatile("mma.sync.aligned.m16n8k16.row.col.f32.f16.f16.f32 " \
                 "{%0,%1,%2,%3}, {%4,%5,%6,%7}, {%8,%9}, {%0,%1,%2,%3};" \
                 : "+f"((C)[0]), "+f"((C)[1]), "+f"((C)[2]), "+f"((C)[3]) \
                 : "r"(A0), "r"(A1), "r"(A2), "r"(A3), "r"(B0), "r"(B1))

// ---- gemm pipeline constants (identical to proven R12 config) ----
#define NCH     8
#define STG     3
#define A_BYTES 16384
#define B_BYTES 8192
#define STAGE_B 24576
#define MBAR_OFF (STG * STAGE_B)         // 73728
#define SMEM_TOT (MBAR_OFF + 64)

// ============================================================================
__global__ void init_flags() {
    for (int i = threadIdx.x; i < 8 * NBLK; i += 256) g_flag[i] = 0;
    if (threadIdx.x == 0) g_wflag = 0;
}

// ============================================================================
// Merged kernel: consumer CTAs (bid<392) overlap with W-prep + pool producers.
// ============================================================================
__global__ __launch_bounds__(256, 3)
void fused(const float* __restrict__ x,
           const float* __restrict__ gamma,
           const float* __restrict__ beta,
           const float* __restrict__ mean,
           const float* __restrict__ var,
           const float* __restrict__ w,
           float* __restrict__ out) {
    extern __shared__ char smem[];
    const int bid = blockIdx.x;
    const int tid = threadIdx.x;

    // ======================== W-prep producers =============================
    if (bid >= NCON && bid < NCON + NWB) {
        int wx = bid - NCON;
        int e0 = (wx * 256 + tid) * 16;          // 16 elements per thread
#pragma unroll
        for (int q = 0; q < 4; q++) {
            int base = e0 + q * 4;
            float4 v = *(const float4*)(w + base);
            int m = base >> 9;
            int k = base & 511;
            int mr = m & 127;
            uint32_t u   = (uint32_t)((k & 63) >> 3);
            uint32_t sub = (uint32_t)(k & 7) * 2;
            __half h[4] = {__float2half(v.x), __float2half(v.y),
                           __float2half(v.z), __float2half(v.w)};
            char* d = (char*)g_wh + ((size_t)(k >> 6) * 2 + (m >> 7)) * 16384
                    + (uint32_t)mr * 128 + ((u ^ (uint32_t)(mr & 7)) * 16) + sub;
            *(uint2*)d = *(uint2*)h;
        }
        __syncthreads();
        if (tid == 0) {
            asm volatile("fence.acq_rel.gpu;" ::: "memory");
            atomicAdd(&g_wflag, 1);
        }
        return;
    }

    // ======================== pool producers ================================
    if (bid >= NCON + NWB) {
        int p = bid - (NCON + NWB);
        const int chunk = p / NBLK;          // chunk-major: chunk 0 blocks first
        const int nblk  = p - chunk * NBLK;
        const int n0 = nblk * 64;
        const int c0 = chunk * 64;

        float* ssc = (float*)smem;           // [64]
        float* ssh = ssc + 64;               // [64]
        if (tid < 64) {
            int c = c0 + tid;
            float sc = gamma[c] * rsqrtf(var[c] + 1e-5f);
            ssc[tid] = sc;
            ssh[tid] = beta[c] - mean[c] * sc;
        }
        __syncthreads();

        const int pr2 = tid & 31;
        const int cq  = tid >> 5;
        const int nn = n0 + 2 * pr2;
        const int b  = nn / NPB;
        const int pp = nn - b * NPB;
        const int ho = pp / WO, wo = pp - ho * WO;
        const float* xb = x + ((size_t)b * CIN * H_ + 2 * ho) * W_ + 2 * wo;

        char* base = (char*)g_yh + ((size_t)chunk * NBLK + nblk) * 8192;
        const uint32_t sub = (uint32_t)(pr2 & 3) * 4;
        const uint32_t upr = (uint32_t)(pr2 >> 2);

#pragma unroll
        for (int pass = 0; pass < 2; pass++) {
            float4 R0[4], R1[4];
#pragma unroll
            for (int t = 0; t < 4; t++) {        // batch loads: MLP 8
                int cl = (pass * 4 + t) * 8 + cq;
                const float* xp = xb + (size_t)(c0 + cl) * HW;
                R0[t] = *(const float4*)xp;
                R1[t] = *(const float4*)(xp + W_);
            }
#pragma unroll
            for (int t = 0; t < 4; t++) {
                int cl = (pass * 4 + t) * 8 + cq;
                float sc = ssc[cl], sh = ssh[cl];
                float v0 = fmaxf(fmaf(R0[t].x, sc, sh), 0.f) + fmaxf(fmaf(R0[t].y, sc, sh), 0.f)
                         + fmaxf(fmaf(R1[t].x, sc, sh), 0.f) + fmaxf(fmaf(R1[t].y, sc, sh), 0.f);
                float v1 = fmaxf(fmaf(R0[t].z, sc, sh), 0.f) + fmaxf(fmaf(R0[t].w, sc, sh), 0.f)
                         + fmaxf(fmaf(R1[t].z, sc, sh), 0.f) + fmaxf(fmaf(R1[t].w, sc, sh), 0.f);
                __half h0 = __float2half(v0 * 0.25f);
                __half h1 = __float2half(v1 * 0.25f);
                uint32_t hp = ((uint32_t)__half_as_ushort(h1) << 16) | __half_as_ushort(h0);
                *(uint32_t*)(base + (uint32_t)cl * 128
                             + ((upr ^ (uint32_t)(cl & 7)) * 16) + sub) = hp;
            }
        }
        __syncthreads();
        if (tid == 0) set_flag(&g_flag[chunk * NBLK + nblk]);
        return;
    }

    // ======================== consumers (gemm, R12-proven) =================
    const uint32_t sb = smem_u32(smem);
    const int lid = tid & 31, wid = tid >> 5;
    const int nblk = bid >> 1;
    const int mblk = bid & 1;
    const int n0 = nblk * 64;
    const int m0 = mblk * 128;

    if (tid == 0) {
#pragma unroll
        for (int s = 0; s < STG; s++) MBAR_INIT(sb + MBAR_OFF + s * 8, 1);
    }
    __syncthreads();

    // wait for W conversion (all 32 blocks)
    if (tid == 0) {
        while (ld_acq(&g_wflag) != NWB) __nanosleep(128);
        FENCE_PROXY();
    }

    const int wm = wid & 3, wn = wid >> 2;
    const int half = lid >> 4;
    const int rkb  = (lid & 7) + (((lid >> 3) & 1) << 3);
    const int arow0 = wm * 32 + (lid & 15);

    float acc[2][4][4];
#pragma unroll
    for (int a = 0; a < 2; a++)
#pragma unroll
        for (int b = 0; b < 4; b++)
#pragma unroll
            for (int c = 0; c < 4; c++) acc[a][b][c] = 0.f;

    int issued = 0;
    for (int i = 0; i < NCH; i++) {
        __syncthreads();                      // readers of reused slot done
        if (tid == 0) {
            // blocking: chunk i must be issued
            while (issued <= i) {
                while (!ld_acq(&g_flag[issued * NBLK + nblk])) __nanosleep(128);
                FENCE_PROXY();
                const int slot = issued % STG;
                const uint32_t s = sb + (uint32_t)slot * STAGE_B;
                const uint32_t mb = sb + MBAR_OFF + slot * 8;
                MBAR_EXPECT_TX(mb, STAGE_B);
                BULK_G2S(s, (const char*)g_wh + ((size_t)issued * 2 + mblk) * A_BYTES, A_BYTES, mb);
                BULK_G2S(s + A_BYTES, (const char*)g_yh + ((size_t)issued * NBLK + nblk) * B_BYTES, B_BYTES, mb);
                issued++;
            }
            // opportunistic lookahead up to i+2 (slot-safe)
            int lim = (i + 2 < NCH - 1) ? (i + 2) : (NCH - 1);
            while (issued <= lim && ld_acq(&g_flag[issued * NBLK + nblk])) {
                FENCE_PROXY();
                const int slot = issued % STG;
                const uint32_t s = sb + (uint32_t)slot * STAGE_B;
                const uint32_t mb = sb + MBAR_OFF + slot * 8;
                MBAR_EXPECT_TX(mb, STAGE_B);
                BULK_G2S(s, (const char*)g_wh + ((size_t)issued * 2 + mblk) * A_BYTES, A_BYTES, mb);
                BULK_G2S(s + A_BYTES, (const char*)g_yh + ((size_t)issued * NBLK + nblk) * B_BYTES, B_BYTES, mb);
                issued++;
            }
        }
        mbar_wait(sb + MBAR_OFF + (i % STG) * 8, (uint32_t)((i / STG) & 1));

        const uint32_t sA = sb + (uint32_t)(i % STG) * STAGE_B;
        const uint32_t sB = sA + A_BYTES;
#pragma unroll
        for (int ks = 0; ks < 4; ks++) {
            const int rk = ks * 16 + rkb;
            const uint32_t brow = sB + (uint32_t)rk * 128;
            uint32_t bf[8];
#pragma unroll
            for (int q = 0; q < 2; q++) {
                uint32_t u = (uint32_t)(wn * 4 + 2 * q + half);
                LDSM4T(bf[q*4+0], bf[q*4+1], bf[q*4+2], bf[q*4+3],
                       brow + ((u ^ (uint32_t)(rk & 7)) * 16));
            }
            const uint32_t ua = (uint32_t)(2 * ks + half);
#pragma unroll
            for (int mt = 0; mt < 2; mt++) {
                int rA = arow0 + mt * 16;
                uint32_t a0, a1, a2, a3;
                LDSM4(a0, a1, a2, a3,
                      sA + (uint32_t)rA * 128 + ((ua ^ (uint32_t)(rA & 7)) * 16));
                MMAF16(acc[mt][0], a0, a1, a2, a3, bf[0], bf[1]);
                MMAF16(acc[mt][1], a0, a1, a2, a3, bf[2], bf[3]);
                MMAF16(acc[mt][2], a0, a1, a2, a3, bf[4], bf[5]);
                MMAF16(acc[mt][3], a0, a1, a2, a3, bf[6], bf[7]);
            }
        }
    }

    // epilogue
#pragma unroll
    for (int mt = 0; mt < 2; mt++) {
#pragma unroll
        for (int nt = 0; nt < 4; nt++) {
            int m = m0 + wm * 32 + mt * 16 + (lid >> 2);
            int n = n0 + wn * 32 + nt * 8 + ((lid & 3) << 1);
            int b2 = n / NPB, p2 = n - b2 * NPB;
            float* o = out + ((size_t)b2 * COUT + m) * NPB + p2;
            *(float2*)o = make_float2(acc[mt][nt][0], acc[mt][nt][1]);
            *(float2*)(o + 8 * NPB) = make_float2(acc[mt][nt][2], acc[mt][nt][3]);
        }
    }
}

// ============================================================================
extern "C" void kernel_launch(void* const* d_in, const int* in_sizes, int n_in,
                              void* d_out, int out_size) {
    const float* x  = (const float*)d_in[0];
    const float* gw = (const float*)d_in[1];
    const float* gb = (const float*)d_in[2];
    const float* gm = (const float*)d_in[3];
    const float* gv = (const float*)d_in[4];
    const float* cw = (const float*)d_in[5];
    float* out = (float*)d_out;

    cudaFuncSetAttribute(fused, cudaFuncAttributeMaxDynamicSharedMemorySize, SMEM_TOT);

    init_flags<<<1, 256>>>();
    fused<<<GRID, 256, SMEM_TOT>>>(x, gw, gb, gm, gv, cw, out);
}

// round 14
// speedup vs baseline: 1.9247x; 1.9247x over previous
#include <cuda_runtime.h>
#include <cuda_fp16.h>
#include <cstdint>

// ---------------- problem constants ----------------
#define B_    16
#define CIN   512
#define COUT  256
#define H_    56
#define W_    56
#define HO    28
#define WO    28
#define NPB   784
#define NTOT  (B_ * NPB)          // 12544
#define HW    (H_ * W_)
#define NBLK  (NTOT / 64)         // 196

// grid roles: W-prep FIRST, pool producers (chunk-major), consumers LAST
#define NWB   32                  // W-prep blocks
#define NPOOL 1568                // pool blocks (8 chunks x 196 nblk)
#define NCON  392                 // gemm consumer CTAs (196 nblk x 2 mblk)
#define GRID  (NWB + NPOOL + NCON)

// scratch (pre-swizzled; g_yh is k-major per 64x64 tile)
__device__ __align__(1024) __half g_wh[8 * 2 * 128 * 64];
__device__ __align__(1024) __half g_yh[(size_t)8 * NBLK * 64 * 64];
__device__ int g_flag[8 * NBLK];
__device__ int g_wflag;

__device__ __forceinline__ uint32_t smem_u32(const void* p) {
    uint32_t a;
    asm("{ .reg .u64 t; cvta.to.shared.u64 t, %1; cvt.u32.u64 %0, t; }" : "=r"(a) : "l"(p));
    return a;
}
__device__ __forceinline__ int ld_acq(const int* p) {
    int v;
    asm volatile("ld.acquire.gpu.global.b32 %0, [%1];" : "=r"(v) : "l"(p) : "memory");
    return v;
}
__device__ __forceinline__ void set_flag(int* p) {
    asm volatile("fence.acq_rel.gpu;" ::: "memory");
    atomicExch(p, 1);
}
#define FENCE_PROXY() asm volatile("fence.proxy.async;" ::: "memory")
#define MBAR_INIT(a, c) \
    asm volatile("mbarrier.init.shared.b64 [%0], %1;" :: "r"(a), "r"(c) : "memory")
#define MBAR_EXPECT_TX(a, b) \
    asm volatile("mbarrier.arrive.expect_tx.shared.b64 _, [%0], %1;" :: "r"(a), "r"(b) : "memory")
__device__ __forceinline__ void mbar_wait(uint32_t a, uint32_t parity) {
    asm volatile(
        "{\n\t.reg .pred P;\n\t"
        "W_%=:\n\t"
        "mbarrier.try_wait.parity.acquire.cta.shared::cta.b64 P, [%0], %1, 0x989680;\n\t"
        "@P bra.uni D_%=;\n\t"
        "bra.uni W_%=;\n\t"
        "D_%=:\n\t}"
        :: "r"(a), "r"(parity) : "memory");
}
#define BULK_G2S(dst, src, bytes, mbar) \
    asm volatile("cp.async.bulk.shared::cluster.global.mbarrier::complete_tx::bytes " \
                 "[%0], [%1], %2, [%3];" \
                 :: "r"(dst), "l"(src), "r"(bytes), "r"(mbar) : "memory")
#define LDSM4(R0, R1, R2, R3, A) \
    asm volatile("ldmatrix.sync.aligned.m8n8.x4.shared.b16 {%0,%1,%2,%3}, [%4];" \
                 : "=r"(R0), "=r"(R1), "=r"(R2), "=r"(R3) : "r"(A))
#define LDSM4T(R0, R1, R2, R3, A) \
    asm volatile("ldmatrix.sync.aligned.m8n8.x4.trans.shared.b16 {%0,%1,%2,%3}, [%4];" \
                 : "=r"(R0), "=r"(R1), "=r"(R2), "=r"(R3) : "r"(A))
#define MMAF16(C, A0, A1, A2, A3, B0, B1) \
    asm volatile("mma.sync.aligned.m16n8k16.row.col.f32.f16.f16.f32 " \
                 "{%0,%1,%2,%3}, {%4,%5,%6,%7}, {%8,%9}, {%0,%1,%2,%3};" \
                 : "+f"((C)[0]), "+f"((C)[1]), "+f"((C)[2]), "+f"((C)[3]) \
                 : "r"(A0), "r"(A1), "r"(A2), "r"(A3), "r"(B0), "r"(B1))

// ---- gemm pipeline constants (identical to proven R12 config) ----
#define NCH     8
#define STG     3
#define A_BYTES 16384
#define B_BYTES 8192
#define STAGE_B 24576
#define MBAR_OFF (STG * STAGE_B)         // 73728
#define SMEM_TOT (MBAR_OFF + 64)

// ============================================================================
__global__ void init_flags() {
    for (int i = threadIdx.x; i < 8 * NBLK; i += 256) g_flag[i] = 0;
    if (threadIdx.x == 0) g_wflag = 0;
}

// ============================================================================
// Merged kernel, producers-first scheduling.
// ============================================================================
__global__ __launch_bounds__(256, 3)
void fused(const float* __restrict__ x,
           const float* __restrict__ gamma,
           const float* __restrict__ beta,
           const float* __restrict__ mean,
           const float* __restrict__ var,
           const float* __restrict__ w,
           float* __restrict__ out) {
    extern __shared__ char smem[];
    const int bid = blockIdx.x;
    const int tid = threadIdx.x;

    // ======================== W-prep producers (bids 0..31) ================
    if (bid < NWB) {
        int e0 = (bid * 256 + tid) * 16;          // 16 elements per thread
#pragma unroll
        for (int q = 0; q < 4; q++) {
            int base = e0 + q * 4;
            float4 v = *(const float4*)(w + base);
            int m = base >> 9;
            int k = base & 511;
            int mr = m & 127;
            uint32_t u   = (uint32_t)((k & 63) >> 3);
            uint32_t sub = (uint32_t)(k & 7) * 2;
            __half h[4] = {__float2half(v.x), __float2half(v.y),
                           __float2half(v.z), __float2half(v.w)};
            char* d = (char*)g_wh + ((size_t)(k >> 6) * 2 + (m >> 7)) * 16384
                    + (uint32_t)mr * 128 + ((u ^ (uint32_t)(mr & 7)) * 16) + sub;
            *(uint2*)d = *(uint2*)h;
        }
        __syncthreads();
        if (tid == 0) {
            asm volatile("fence.acq_rel.gpu;" ::: "memory");
            atomicAdd(&g_wflag, 1);
        }
        return;
    }

    // ======================== pool producers (bids 32..1599) ===============
    if (bid < NWB + NPOOL) {
        int p = bid - NWB;
        const int chunk = p / NBLK;          // chunk-major: chunk 0 blocks first
        const int nblk  = p - chunk * NBLK;
        const int n0 = nblk * 64;
        const int c0 = chunk * 64;

        float* ssc = (float*)smem;           // [64]
        float* ssh = ssc + 64;               // [64]
        if (tid < 64) {
            int c = c0 + tid;
            float sc = gamma[c] * rsqrtf(var[c] + 1e-5f);
            ssc[tid] = sc;
            ssh[tid] = beta[c] - mean[c] * sc;
        }
        __syncthreads();

        const int pr2 = tid & 31;
        const int cq  = tid >> 5;
        const int nn = n0 + 2 * pr2;
        const int b  = nn / NPB;
        const int pp = nn - b * NPB;
        const int ho = pp / WO, wo = pp - ho * WO;
        const float* xb = x + ((size_t)b * CIN * H_ + 2 * ho) * W_ + 2 * wo;

        char* base = (char*)g_yh + ((size_t)chunk * NBLK + nblk) * 8192;
        const uint32_t sub = (uint32_t)(pr2 & 3) * 4;
        const uint32_t upr = (uint32_t)(pr2 >> 2);

#pragma unroll
        for (int pass = 0; pass < 2; pass++) {
            float4 R0[4], R1[4];
#pragma unroll
            for (int t = 0; t < 4; t++) {        // batch loads: MLP 8
                int cl = (pass * 4 + t) * 8 + cq;
                const float* xp = xb + (size_t)(c0 + cl) * HW;
                R0[t] = *(const float4*)xp;
                R1[t] = *(const float4*)(xp + W_);
            }
#pragma unroll
            for (int t = 0; t < 4; t++) {
                int cl = (pass * 4 + t) * 8 + cq;
                float sc = ssc[cl], sh = ssh[cl];
                float v0 = fmaxf(fmaf(R0[t].x, sc, sh), 0.f) + fmaxf(fmaf(R0[t].y, sc, sh), 0.f)
                         + fmaxf(fmaf(R1[t].x, sc, sh), 0.f) + fmaxf(fmaf(R1[t].y, sc, sh), 0.f);
                float v1 = fmaxf(fmaf(R0[t].z, sc, sh), 0.f) + fmaxf(fmaf(R0[t].w, sc, sh), 0.f)
                         + fmaxf(fmaf(R1[t].z, sc, sh), 0.f) + fmaxf(fmaf(R1[t].w, sc, sh), 0.f);
                __half h0 = __float2half(v0 * 0.25f);
                __half h1 = __float2half(v1 * 0.25f);
                uint32_t hp = ((uint32_t)__half_as_ushort(h1) << 16) | __half_as_ushort(h0);
                *(uint32_t*)(base + (uint32_t)cl * 128
                             + ((upr ^ (uint32_t)(cl & 7)) * 16) + sub) = hp;
            }
        }
        __syncthreads();
        if (tid == 0) set_flag(&g_flag[chunk * NBLK + nblk]);
        return;
    }

    // ======================== consumers (bids 1600..1991) ==================
    const int cid = bid - (NWB + NPOOL);
    const uint32_t sb = smem_u32(smem);
    const int lid = tid & 31, wid = tid >> 5;
    const int nblk = cid >> 1;
    const int mblk = cid & 1;
    const int n0 = nblk * 64;
    const int m0 = mblk * 128;

    if (tid == 0) {
#pragma unroll
        for (int s = 0; s < STG; s++) MBAR_INIT(sb + MBAR_OFF + s * 8, 1);
    }
    __syncthreads();

    // wait for W conversion (all 32 blocks) — done long before consumers start
    if (tid == 0) {
        while (ld_acq(&g_wflag) != NWB) __nanosleep(128);
        FENCE_PROXY();
    }

    const int wm = wid & 3, wn = wid >> 2;
    const int half = lid >> 4;
    const int rkb  = (lid & 7) + (((lid >> 3) & 1) << 3);
    const int arow0 = wm * 32 + (lid & 15);

    float acc[2][4][4];
#pragma unroll
    for (int a = 0; a < 2; a++)
#pragma unroll
        for (int b = 0; b < 4; b++)
#pragma unroll
            for (int c = 0; c < 4; c++) acc[a][b][c] = 0.f;

    int issued = 0;
    for (int i = 0; i < NCH; i++) {
        __syncthreads();                      // readers of reused slot done
        if (tid == 0) {
            // blocking: chunk i must be issued
            while (issued <= i) {
                while (!ld_acq(&g_flag[issued * NBLK + nblk])) __nanosleep(128);
                FENCE_PROXY();
                const int slot = issued % STG;
                const uint32_t s = sb + (uint32_t)slot * STAGE_B;
                const uint32_t mb = sb + MBAR_OFF + slot * 8;
                MBAR_EXPECT_TX(mb, STAGE_B);
                BULK_G2S(s, (const char*)g_wh + ((size_t)issued * 2 + mblk) * A_BYTES, A_BYTES, mb);
                BULK_G2S(s + A_BYTES, (const char*)g_yh + ((size_t)issued * NBLK + nblk) * B_BYTES, B_BYTES, mb);
                issued++;
            }
            // opportunistic lookahead up to i+2 (slot-safe)
            int lim = (i + 2 < NCH - 1) ? (i + 2) : (NCH - 1);
            while (issued <= lim && ld_acq(&g_flag[issued * NBLK + nblk])) {
                FENCE_PROXY();
                const int slot = issued % STG;
                const uint32_t s = sb + (uint32_t)slot * STAGE_B;
                const uint32_t mb = sb + MBAR_OFF + slot * 8;
                MBAR_EXPECT_TX(mb, STAGE_B);
                BULK_G2S(s, (const char*)g_wh + ((size_t)issued * 2 + mblk) * A_BYTES, A_BYTES, mb);
                BULK_G2S(s + A_BYTES, (const char*)g_yh + ((size_t)issued * NBLK + nblk) * B_BYTES, B_BYTES, mb);
                issued++;
            }
        }
        mbar_wait(sb + MBAR_OFF + (i % STG) * 8, (uint32_t)((i / STG) & 1));

        const uint32_t sA = sb + (uint32_t)(i % STG) * STAGE_B;
        const uint32_t sB = sA + A_BYTES;
#pragma unroll
        for (int ks = 0; ks < 4; ks++) {
            const int rk = ks * 16 + rkb;
            const uint32_t brow = sB + (uint32_t)rk * 128;
            uint32_t bf[8];
#pragma unroll
            for (int q = 0; q < 2; q++) {
                uint32_t u = (uint32_t)(wn * 4 + 2 * q + half);
                LDSM4T(bf[q*4+0], bf[q*4+1], bf[q*4+2], bf[q*4+3],
                       brow + ((u ^ (uint32_t)(rk & 7)) * 16));
            }
            const uint32_t ua = (uint32_t)(2 * ks + half);
#pragma unroll
            for (int mt = 0; mt < 2; mt++) {
                int rA = arow0 + mt * 16;
                uint32_t a0, a1, a2, a3;
                LDSM4(a0, a1, a2, a3,
                      sA + (uint32_t)rA * 128 + ((ua ^ (uint32_t)(rA & 7)) * 16));
                MMAF16(acc[mt][0], a0, a1, a2, a3, bf[0], bf[1]);
                MMAF16(acc[mt][1], a0, a1, a2, a3, bf[2], bf[3]);
                MMAF16(acc[mt][2], a0, a1, a2, a3, bf[4], bf[5]);
                MMAF16(acc[mt][3], a0, a1, a2, a3, bf[6], bf[7]);
            }
        }
    }

    // epilogue
#pragma unroll
    for (int mt = 0; mt < 2; mt++) {
#pragma unroll
        for (int nt = 0; nt < 4; nt++) {
            int m = m0 + wm * 32 + mt * 16 + (lid >> 2);
            int n = n0 + wn * 32 + nt * 8 + ((lid & 3) << 1);
            int b2 = n / NPB, p2 = n - b2 * NPB;
            float* o = out + ((size_t)b2 * COUT + m) * NPB + p2;
            *(float2*)o = make_float2(acc[mt][nt][0], acc[mt][nt][1]);
            *(float2*)(o + 8 * NPB) = make_float2(acc[mt][nt][2], acc[mt][nt][3]);
        }
    }
}

// ============================================================================
extern "C" void kernel_launch(void* const* d_in, const int* in_sizes, int n_in,
                              void* d_out, int out_size) {
    const float* x  = (const float*)d_in[0];
    const float* gw = (const float*)d_in[1];
    const float* gb = (const float*)d_in[2];
    const float* gm = (const float*)d_in[3];
    const float* gv = (const float*)d_in[4];
    const float* cw = (const float*)d_in[5];
    float* out = (float*)d_out;

    cudaFuncSetAttribute(fused, cudaFuncAttributeMaxDynamicSharedMemorySize, SMEM_TOT);

    init_flags<<<1, 256>>>();
    fused<<<GRID, 256, SMEM_TOT>>>(x, gw, gb, gm, gv, cw, out);
}

// round 15
// speedup vs baseline: 1.9933x; 1.0356x over previous
#include <cuda_runtime.h>
#include <cuda_fp16.h>
#include <cstdint>

// ---------------- problem constants ----------------
#define B_    16
#define CIN   512
#define COUT  256
#define H_    56
#define W_    56
#define HO    28
#define WO    28
#define NPB   784
#define NTOT  (B_ * NPB)          // 12544
#define HW    (H_ * W_)
#define NBLK  (NTOT / 64)         // 196
#define NPOOL 1568                // 8 chunks x 196 nblk
#define NCONS 392                 // consumer roles (196 nblk x 2 mblk)
#define NCTA  444                 // exactly 3 per SM -> single wave, all resident

// scratch (pre-swizzled; g_yh is k-major per 64x64 tile)
__device__ __align__(1024) __half g_wh[8 * 2 * 128 * 64];
__device__ __align__(1024) __half g_yh[(size_t)8 * NBLK * 64 * 64];
__device__ int g_flag[NPOOL];
__device__ int g_wflag;

__device__ __forceinline__ uint32_t smem_u32(const void* p) {
    uint32_t a;
    asm("{ .reg .u64 t; cvta.to.shared.u64 t, %1; cvt.u32.u64 %0, t; }" : "=r"(a) : "l"(p));
    return a;
}
__device__ __forceinline__ int ld_acq(const int* p) {
    int v;
    asm volatile("ld.acquire.gpu.global.b32 %0, [%1];" : "=r"(v) : "l"(p) : "memory");
    return v;
}
__device__ __forceinline__ void set_flag(int* p) {
    asm volatile("fence.acq_rel.gpu;" ::: "memory");
    atomicExch(p, 1);
}
#define FENCE_PROXY() asm volatile("fence.proxy.async;" ::: "memory")
#define MBAR_INIT(a, c) \
    asm volatile("mbarrier.init.shared.b64 [%0], %1;" :: "r"(a), "r"(c) : "memory")
#define MBAR_EXPECT_TX(a, b) \
    asm volatile("mbarrier.arrive.expect_tx.shared.b64 _, [%0], %1;" :: "r"(a), "r"(b) : "memory")
__device__ __forceinline__ void mbar_wait(uint32_t a, uint32_t parity) {
    asm volatile(
        "{\n\t.reg .pred P;\n\t"
        "W_%=:\n\t"
        "mbarrier.try_wait.parity.acquire.cta.shared::cta.b64 P, [%0], %1, 0x989680;\n\t"
        "@P bra.uni D_%=;\n\t"
        "bra.uni W_%=;\n\t"
        "D_%=:\n\t}"
        :: "r"(a), "r"(parity) : "memory");
}
#define BULK_G2S(dst, src, bytes, mbar) \
    asm volatile("cp.async.bulk.shared::cluster.global.mbarrier::complete_tx::bytes " \
                 "[%0], [%1], %2, [%3];" \
                 :: "r"(dst), "l"(src), "r"(bytes), "r"(mbar) : "memory")
#define LDSM4(R0, R1, R2, R3, A) \
    asm volatile("ldmatrix.sync.aligned.m8n8.x4.shared.b16 {%0,%1,%2,%3}, [%4];" \
                 : "=r"(R0), "=r"(R1), "=r"(R2), "=r"(R3) : "r"(A))
#define LDSM4T(R0, R1, R2, R3, A) \
    asm volatile("ldmatrix.sync.aligned.m8n8.x4.trans.shared.b16 {%0,%1,%2,%3}, [%4];" \
                 : "=r"(R0), "=r"(R1), "=r"(R2), "=r"(R3) : "r"(A))
#define MMAF16(C, A0, A1, A2, A3, B0, B1) \
    asm volatile("mma.sync.aligned.m16n8k16.row.col.f32.f16.f16.f32 " \
                 "{%0,%1,%2,%3}, {%4,%5,%6,%7}, {%8,%9}, {%0,%1,%2,%3};" \
                 : "+f"((C)[0]), "+f"((C)[1]), "+f"((C)[2]), "+f"((C)[3]) \
                 : "r"(A0), "r"(A1), "r"(A2), "r"(A3), "r"(B0), "r"(B1))

// ---- gemm pipeline constants (proven R12/R14 config) ----
#define NCH     8
#define STG     3
#define A_BYTES 16384
#define B_BYTES 8192
#define STAGE_B 24576
#define MBAR_OFF (STG * STAGE_B)         // 73728
#define SMEM_TOT (MBAR_OFF + 64)

// ============================================================================
__global__ void init_flags() {
    for (int i = threadIdx.x; i < NPOOL; i += 256) g_flag[i] = 0;
    if (threadIdx.x == 0) g_wflag = 0;
}

// ============================================================================
// Persistent dual-role kernel: every CTA pools 3-4 tiles AND (bid<392) runs
// one GEMM tile, interleaved. Single wave (444 CTAs @ 3/SM) => deadlock-free.
// ============================================================================
__global__ __launch_bounds__(256, 3)
void fused(const float* __restrict__ x,
           const float* __restrict__ gamma,
           const float* __restrict__ beta,
           const float* __restrict__ mean,
           const float* __restrict__ var,
           const float* __restrict__ w,
           float* __restrict__ out) {
    extern __shared__ char smem[];
    const uint32_t sb = smem_u32(smem);
    const int bid = blockIdx.x;
    const int tid = threadIdx.x;
    const int lid = tid & 31, wid = tid >> 5;
    const bool is_cons = (bid < NCONS);
    const int nblk = bid >> 1;               // consumer tile
    const int mblk = bid & 1;

    if (is_cons && tid == 0) {
#pragma unroll
        for (int s = 0; s < STG; s++) MBAR_INIT(sb + MBAR_OFF + s * 8, 1);
    }
    __syncthreads();

    // ---- W-prep: CTAs 0..31, before their pool work (~1.5us) ----
    if (bid < 32) {
        int e0 = (bid * 256 + tid) * 16;
#pragma unroll
        for (int q = 0; q < 4; q++) {
            int base = e0 + q * 4;
            float4 v = *(const float4*)(w + base);
            int m = base >> 9;
            int k = base & 511;
            int mr = m & 127;
            uint32_t u   = (uint32_t)((k & 63) >> 3);
            uint32_t sub = (uint32_t)(k & 7) * 2;
            __half h[4] = {__float2half(v.x), __float2half(v.y),
                           __float2half(v.z), __float2half(v.w)};
            char* d = (char*)g_wh + ((size_t)(k >> 6) * 2 + (m >> 7)) * 16384
                    + (uint32_t)mr * 128 + ((u ^ (uint32_t)(mr & 7)) * 16) + sub;
            *(uint2*)d = *(uint2*)h;
        }
        __syncthreads();
        if (tid == 0) {
            asm volatile("fence.acq_rel.gpu;" ::: "memory");
            atomicAdd(&g_wflag, 1);
        }
    }

    // ---- pool tile: BN+ReLU+pool -> fp16 k-major swizzled, then flag ----
    auto pool_tile = [&](int t) {
        const int chunk = t / NBLK;
        const int nb = t - chunk * NBLK;
        const int n0p = nb * 64, c0 = chunk * 64;
        const int pr2 = tid & 31;
        const int cq  = tid >> 5;             // constant per warp -> bcast const loads
        const int nn = n0p + 2 * pr2;
        const int b  = nn / NPB;
        const int pp = nn - b * NPB;
        const int ho = pp / WO, wo = pp - ho * WO;
        const float* xb = x + ((size_t)b * CIN * H_ + 2 * ho) * W_ + 2 * wo;
        char* base = (char*)g_yh + ((size_t)chunk * NBLK + nb) * 8192;
        const uint32_t sub = (uint32_t)(pr2 & 3) * 4;
        const uint32_t upr = (uint32_t)(pr2 >> 2);
#pragma unroll
        for (int pass = 0; pass < 4; pass++) {
            float4 R0[2], R1[2];
#pragma unroll
            for (int t2 = 0; t2 < 2; t2++) {
                int cl = pass * 16 + t2 * 8 + cq;
                const float* xp = xb + (size_t)(c0 + cl) * HW;
                R0[t2] = *(const float4*)xp;
                R1[t2] = *(const float4*)(xp + W_);
            }
#pragma unroll
            for (int t2 = 0; t2 < 2; t2++) {
                int cl = pass * 16 + t2 * 8 + cq;
                int c = c0 + cl;
                float sc = gamma[c] * rsqrtf(var[c] + 1e-5f);
                float sh = beta[c] - mean[c] * sc;
                float v0 = fmaxf(fmaf(R0[t2].x, sc, sh), 0.f) + fmaxf(fmaf(R0[t2].y, sc, sh), 0.f)
                         + fmaxf(fmaf(R1[t2].x, sc, sh), 0.f) + fmaxf(fmaf(R1[t2].y, sc, sh), 0.f);
                float v1 = fmaxf(fmaf(R0[t2].z, sc, sh), 0.f) + fmaxf(fmaf(R0[t2].w, sc, sh), 0.f)
                         + fmaxf(fmaf(R1[t2].z, sc, sh), 0.f) + fmaxf(fmaf(R1[t2].w, sc, sh), 0.f);
                __half h0 = __float2half(v0 * 0.25f);
                __half h1 = __float2half(v1 * 0.25f);
                uint32_t hp = ((uint32_t)__half_as_ushort(h1) << 16) | __half_as_ushort(h0);
                *(uint32_t*)(base + (uint32_t)cl * 128
                             + ((upr ^ (uint32_t)(cl & 7)) * 16) + sub) = hp;
            }
        }
        __syncthreads();
        if (tid == 0) set_flag(&g_flag[t]);
    };

    // ---- consumer state ----
    const int wm = wid & 3, wn = wid >> 2;
    const int half = lid >> 4;
    const int rkb  = (lid & 7) + (((lid >> 3) & 1) << 3);
    const int arow0 = wm * 32 + (lid & 15);

    float acc[2][4][4];
#pragma unroll
    for (int a = 0; a < 2; a++)
#pragma unroll
        for (int b = 0; b < 4; b++)
#pragma unroll
            for (int c = 0; c < 4; c++) acc[a][b][c] = 0.f;
    int issued = 0;

    // ---- mma chunk range [i0, i1): flag-gated TMA issue + MMA (R14-proven) ----
    auto mma_run = [&](int i0, int i1) {
        for (int i = i0; i < i1; i++) {
            __syncthreads();                  // readers of reused slot done
            if (tid == 0) {
                while (issued <= i) {
                    while (!ld_acq(&g_flag[issued * NBLK + nblk])) __nanosleep(128);
                    FENCE_PROXY();
                    const int slot = issued % STG;
                    const uint32_t s = sb + (uint32_t)slot * STAGE_B;
                    const uint32_t mb = sb + MBAR_OFF + slot * 8;
                    MBAR_EXPECT_TX(mb, STAGE_B);
                    BULK_G2S(s, (const char*)g_wh + ((size_t)issued * 2 + mblk) * A_BYTES, A_BYTES, mb);
                    BULK_G2S(s + A_BYTES, (const char*)g_yh + ((size_t)issued * NBLK + nblk) * B_BYTES, B_BYTES, mb);
                    issued++;
                }
                int lim = (i + 2 < NCH - 1) ? (i + 2) : (NCH - 1);
                while (issued <= lim && ld_acq(&g_flag[issued * NBLK + nblk])) {
                    FENCE_PROXY();
                    const int slot = issued % STG;
                    const uint32_t s = sb + (uint32_t)slot * STAGE_B;
                    const uint32_t mb = sb + MBAR_OFF + slot * 8;
                    MBAR_EXPECT_TX(mb, STAGE_B);
                    BULK_G2S(s, (const char*)g_wh + ((size_t)issued * 2 + mblk) * A_BYTES, A_BYTES, mb);
                    BULK_G2S(s + A_BYTES, (const char*)g_yh + ((size_t)issued * NBLK + nblk) * B_BYTES, B_BYTES, mb);
                    issued++;
                }
            }
            mbar_wait(sb + MBAR_OFF + (i % STG) * 8, (uint32_t)((i / STG) & 1));

            const uint32_t sA = sb + (uint32_t)(i % STG) * STAGE_B;
            const uint32_t sB = sA + A_BYTES;
#pragma unroll
            for (int ks = 0; ks < 4; ks++) {
                const int rk = ks * 16 + rkb;
                const uint32_t brow = sB + (uint32_t)rk * 128;
                uint32_t bf[8];
#pragma unroll
                for (int q = 0; q < 2; q++) {
                    uint32_t u = (uint32_t)(wn * 4 + 2 * q + half);
                    LDSM4T(bf[q*4+0], bf[q*4+1], bf[q*4+2], bf[q*4+3],
                           brow + ((u ^ (uint32_t)(rk & 7)) * 16));
                }
                const uint32_t ua = (uint32_t)(2 * ks + half);
#pragma unroll
                for (int mt = 0; mt < 2; mt++) {
                    int rA = arow0 + mt * 16;
                    uint32_t a0, a1, a2, a3;
                    LDSM4(a0, a1, a2, a3,
                          sA + (uint32_t)rA * 128 + ((ua ^ (uint32_t)(rA & 7)) * 16));
                    MMAF16(acc[mt][0], a0, a1, a2, a3, bf[0], bf[1]);
                    MMAF16(acc[mt][1], a0, a1, a2, a3, bf[2], bf[3]);
                    MMAF16(acc[mt][2], a0, a1, a2, a3, bf[4], bf[5]);
                    MMAF16(acc[mt][3], a0, a1, a2, a3, bf[6], bf[7]);
                }
            }
        }
    };

    // ================= interleaved schedule =================
    pool_tile(bid);                               // round 0: chunks 0-1 globally
    if (is_cons && tid == 0) {
        while (ld_acq(&g_wflag) != 32) __nanosleep(128);
        FENCE_PROXY();
    }
    pool_tile(bid + 444);                         // round 1: chunks 2-3 globally
    if (is_cons) mma_run(0, 2);
    pool_tile(bid + 888);                         // round 2: chunks 4-5(+) globally
    if (is_cons) mma_run(2, 4);
    if (bid + 1332 < NPOOL) pool_tile(bid + 1332); // round 3: chunks 6-7 globally
    if (!is_cons) return;
    mma_run(4, 8);

    // ---- epilogue ----
    const int n0 = nblk * 64;
    const int m0 = mblk * 128;
#pragma unroll
    for (int mt = 0; mt < 2; mt++) {
#pragma unroll
        for (int nt = 0; nt < 4; nt++) {
            int m = m0 + wm * 32 + mt * 16 + (lid >> 2);
            int n = n0 + wn * 32 + nt * 8 + ((lid & 3) << 1);
            int b2 = n / NPB, p2 = n - b2 * NPB;
            float* o = out + ((size_t)b2 * COUT + m) * NPB + p2;
            *(float2*)o = make_float2(acc[mt][nt][0], acc[mt][nt][1]);
            *(float2*)(o + 8 * NPB) = make_float2(acc[mt][nt][2], acc[mt][nt][3]);
        }
    }
}

// ============================================================================
extern "C" void kernel_launch(void* const* d_in, const int* in_sizes, int n_in,
                              void* d_out, int out_size) {
    const float* x  = (const float*)d_in[0];
    const float* gw = (const float*)d_in[1];
    const float* gb = (const float*)d_in[2];
    const float* gm = (const float*)d_in[3];
    const float* gv = (const float*)d_in[4];
    const float* cw = (const float*)d_in[5];
    float* out = (float*)d_out;

    cudaFuncSetAttribute(fused, cudaFuncAttributeMaxDynamicSharedMemorySize, SMEM_TOT);

    init_flags<<<1, 256>>>();
    fused<<<NCTA, 256, SMEM_TOT>>>(x, gw, gb, gm, gv, cw, out);
}

// round 17
// speedup vs baseline: 2.6109x; 1.3099x over previous
#include <cuda_runtime.h>
#include <cuda_fp16.h>
#include <cstdint>

// ---------------- problem constants ----------------
#define B_    16
#define CIN   512
#define COUT  256
#define H_    56
#define W_    56
#define HO    28
#define WO    28
#define NPB   784
#define NTOT  (B_ * NPB)          // 12544
#define HW    (H_ * W_)
#define NBLK  (NTOT / 64)         // 196

// scratch (pre-swizzled; g_yh is k-major per 64x64 tile)
__device__ __align__(1024) __half g_wh[8 * 2 * 128 * 64];
__device__ __align__(1024) __half g_yh[(size_t)8 * NBLK * 64 * 64];

__device__ __forceinline__ uint32_t smem_u32(const void* p) {
    uint32_t a;
    asm("{ .reg .u64 t; cvta.to.shared.u64 t, %1; cvt.u32.u64 %0, t; }" : "=r"(a) : "l"(p));
    return a;
}
#define MBAR_INIT(a, c) \
    asm volatile("mbarrier.init.shared.b64 [%0], %1;" :: "r"(a), "r"(c) : "memory")
#define MBAR_EXPECT_TX(a, b) \
    asm volatile("mbarrier.arrive.expect_tx.shared.b64 _, [%0], %1;" :: "r"(a), "r"(b) : "memory")
#define MBAR_ARRIVE(a) \
    asm volatile("mbarrier.arrive.shared.b64 _, [%0];" :: "r"(a) : "memory")
__device__ __forceinline__ void mbar_wait(uint32_t a, uint32_t parity) {
    asm volatile(
        "{\n\t.reg .pred P;\n\t"
        "W_%=:\n\t"
        "mbarrier.try_wait.parity.acquire.cta.shared::cta.b64 P, [%0], %1, 0x989680;\n\t"
        "@P bra.uni D_%=;\n\t"
        "bra.uni W_%=;\n\t"
        "D_%=:\n\t}"
        :: "r"(a), "r"(parity) : "memory");
}
#define BULK_G2S(dst, src, bytes, mbar) \
    asm volatile("cp.async.bulk.shared::cluster.global.mbarrier::complete_tx::bytes " \
                 "[%0], [%1], %2, [%3];" \
                 :: "r"(dst), "l"(src), "r"(bytes), "r"(mbar) : "memory")
#define LDSM4(R0, R1, R2, R3, A) \
    asm volatile("ldmatrix.sync.aligned.m8n8.x4.shared.b16 {%0,%1,%2,%3}, [%4];" \
                 : "=r"(R0), "=r"(R1), "=r"(R2), "=r"(R3) : "r"(A))
#define LDSM4T(R0, R1, R2, R3, A) \
    asm volatile("ldmatrix.sync.aligned.m8n8.x4.trans.shared.b16 {%0,%1,%2,%3}, [%4];" \
                 : "=r"(R0), "=r"(R1), "=r"(R2), "=r"(R3) : "r"(A))
#define MMAF16(C, A0, A1, A2, A3, B0, B1) \
    asm volatile("mma.sync.aligned.m16n8k16.row.col.f32.f16.f16.f32 " \
                 "{%0,%1,%2,%3}, {%4,%5,%6,%7}, {%8,%9}, {%0,%1,%2,%3};" \
                 : "+f"((C)[0]), "+f"((C)[1]), "+f"((C)[2]), "+f"((C)[3]) \
                 : "r"(A0), "r"(A1), "r"(A2), "r"(A3), "r"(B0), "r"(B1))

// ---- gemm pipeline constants ----
#define NCH     8
#define STG     3
#define A_BYTES 16384
#define B_BYTES 8192
#define STAGE_B 24576
#define MBAR_OFF (STG * STAGE_B)         // 73728: full[0..2] then empty[0..2]
#define EMPTY_OFF (MBAR_OFF + 24)
#define SMEM_TOT (MBAR_OFF + 64)

// ============================================================================
// Kernel 1: BN+ReLU+pool -> fp16, direct k-major swizzled write (rows y<8);
//           W fp32 -> fp16 m-major tiles (row y==8). MLP-8 batched loads.
// ============================================================================
__global__ __launch_bounds__(256) void fuse_pool(const float* __restrict__ x,
                                                 const float* __restrict__ gamma,
                                                 const float* __restrict__ beta,
                                                 const float* __restrict__ mean,
                                                 const float* __restrict__ var,
                                                 const float* __restrict__ w) {
    const int tid = threadIdx.x;

    if (blockIdx.y == 8) {                   // ---- W prep (128 blocks used) ----
        if (blockIdx.x < 128) {
            int base = (blockIdx.x * 256 + tid) * 4;
            float4 v = *(const float4*)(w + base);
            int m = base >> 9;
            int k = base & 511;
            int mr = m & 127;
            uint32_t u   = (uint32_t)((k & 63) >> 3);
            uint32_t sub = (uint32_t)(k & 7) * 2;
            __half h[4] = {__float2half(v.x), __float2half(v.y),
                           __float2half(v.z), __float2half(v.w)};
            char* d = (char*)g_wh + ((size_t)(k >> 6) * 2 + (m >> 7)) * 16384
                    + (uint32_t)mr * 128 + ((u ^ (uint32_t)(mr & 7)) * 16) + sub;
            *(uint2*)d = *(uint2*)h;
        }
        return;
    }

    __shared__ float ssc[64], ssh[64];

    const int n0 = blockIdx.x * 64;
    const int c0 = blockIdx.y * 64;

    if (tid < 64) {
        int c = c0 + tid;
        float sc = gamma[c] * rsqrtf(var[c] + 1e-5f);
        ssc[tid] = sc;
        ssh[tid] = beta[c] - mean[c] * sc;
    }
    __syncthreads();

    const int pr2 = tid & 31;                // n = n0 + 2*pr2, +1
    const int cq  = tid >> 5;                // 0..7
    const int nn = n0 + 2 * pr2;
    const int b  = nn / NPB;
    const int p  = nn - b * NPB;
    const int ho = p / WO, wo = p - ho * WO;
    const float* xb = x + ((size_t)b * CIN * H_ + 2 * ho) * W_ + 2 * wo;

    char* base = (char*)g_yh + ((size_t)(c0 >> 6) * NBLK + (n0 >> 6)) * 8192;
    const uint32_t sub = (uint32_t)(pr2 & 3) * 4;
    const uint32_t upr = (uint32_t)(pr2 >> 2);

#pragma unroll
    for (int pass = 0; pass < 2; pass++) {
        float4 R0[4], R1[4];
#pragma unroll
        for (int t = 0; t < 4; t++) {            // batch loads: MLP 8 / thread
            int cl = (pass * 4 + t) * 8 + cq;
            const float* xp = xb + (size_t)(c0 + cl) * HW;
            R0[t] = *(const float4*)xp;
            R1[t] = *(const float4*)(xp + W_);
        }
#pragma unroll
        for (int t = 0; t < 4; t++) {
            int cl = (pass * 4 + t) * 8 + cq;
            float sc = ssc[cl], sh = ssh[cl];
            float v0 = fmaxf(fmaf(R0[t].x, sc, sh), 0.f) + fmaxf(fmaf(R0[t].y, sc, sh), 0.f)
                     + fmaxf(fmaf(R1[t].x, sc, sh), 0.f) + fmaxf(fmaf(R1[t].y, sc, sh), 0.f);
            float v1 = fmaxf(fmaf(R0[t].z, sc, sh), 0.f) + fmaxf(fmaf(R0[t].w, sc, sh), 0.f)
                     + fmaxf(fmaf(R1[t].z, sc, sh), 0.f) + fmaxf(fmaf(R1[t].w, sc, sh), 0.f);
            __half h0 = __float2half(v0 * 0.25f);
            __half h1 = __float2half(v1 * 0.25f);
            uint32_t hp = ((uint32_t)__half_as_ushort(h1) << 16) | __half_as_ushort(h0);
            *(uint32_t*)(base + (uint32_t)cl * 128
                         + ((upr ^ (uint32_t)(cl & 7)) * 16) + sub) = hp;
        }
    }
}

// ============================================================================
// Kernel 2: fp16 GEMM via TMA bulk. BM=128 BN=64 BK=64, 8 chunks.
// Full/empty mbarrier ring (phase-tracked -> no bar.arrive threshold bug):
//   full[s]  count 1 (tx)   : TMA completion
//   empty[s] count 8        : one arrive per warp after chunk reads
// All 3 slots pre-issued; tid0 waits empty parity before issuing i+2.
// ============================================================================
__global__ __launch_bounds__(256, 3) void gemm_mma(float* __restrict__ out) {
    extern __shared__ char smem[];
    const uint32_t sb = smem_u32(smem);
    const int tid = threadIdx.x;
    const int lid = tid & 31, wid = tid >> 5;
    const int nblk = blockIdx.x;
    const int mblk = blockIdx.y;
    const int n0 = nblk * 64;
    const int m0 = mblk * 128;

    if (tid == 0) {
#pragma unroll
        for (int s = 0; s < STG; s++) {
            MBAR_INIT(sb + MBAR_OFF + s * 8, 1);    // full
            MBAR_INIT(sb + EMPTY_OFF + s * 8, 8);   // empty: 8 warp-arrivals
        }
    }
    __syncthreads();

    auto issue = [&](int j) {
        const int slot = j % STG;
        const uint32_t s = sb + (uint32_t)slot * STAGE_B;
        const uint32_t mb = sb + MBAR_OFF + slot * 8;
        MBAR_EXPECT_TX(mb, STAGE_B);
        const char* aSrc = (const char*)g_wh + ((size_t)j * 2 + mblk) * A_BYTES;
        const char* bSrc = (const char*)g_yh + ((size_t)j * NBLK + nblk) * B_BYTES;
        BULK_G2S(s, aSrc, A_BYTES, mb);
        BULK_G2S(s + A_BYTES, bSrc, B_BYTES, mb);
    };

    if (tid == 0) { issue(0); issue(1); issue(2); }   // all 3 slots in flight

    // consumer mapping: 8 warps, warp tile 32m x 32n; B k-major via ldmatrix.trans
    const int wm = wid & 3, wn = wid >> 2;
    const int half = lid >> 4;
    const int rkb  = (lid & 7) + (((lid >> 3) & 1) << 3);
    const int arow0 = wm * 32 + (lid & 15);

    float acc[2][4][4];
#pragma unroll
    for (int a = 0; a < 2; a++)
#pragma unroll
        for (int b = 0; b < 4; b++)
#pragma unroll
            for (int c = 0; c < 4; c++) acc[a][b][c] = 0.f;

    for (int i = 0; i < NCH; i++) {
        // writer side: chunk i+2 reuses slot freed by chunk i-1's readers
        if (tid == 0 && i >= 1 && i + 2 < NCH) {
            mbar_wait(sb + EMPTY_OFF + ((i - 1) % STG) * 8,
                      (uint32_t)(((i - 1) / STG) & 1));
            issue(i + 2);
        }
        mbar_wait(sb + MBAR_OFF + (i % STG) * 8, (uint32_t)((i / STG) & 1));

        const uint32_t sA = sb + (uint32_t)(i % STG) * STAGE_B;
        const uint32_t sB = sA + A_BYTES;
#pragma unroll
        for (int ks = 0; ks < 4; ks++) {
            const int rk = ks * 16 + rkb;
            const uint32_t brow = sB + (uint32_t)rk * 128;
            uint32_t bf[8];
#pragma unroll
            for (int q = 0; q < 2; q++) {
                uint32_t u = (uint32_t)(wn * 4 + 2 * q + half);
                LDSM4T(bf[q*4+0], bf[q*4+1], bf[q*4+2], bf[q*4+3],
                       brow + ((u ^ (uint32_t)(rk & 7)) * 16));
            }
            const uint32_t ua = (uint32_t)(2 * ks + half);
#pragma unroll
            for (int mt = 0; mt < 2; mt++) {
                int rA = arow0 + mt * 16;
                uint32_t a0, a1, a2, a3;
                LDSM4(a0, a1, a2, a3,
                      sA + (uint32_t)rA * 128 + ((ua ^ (uint32_t)(rA & 7)) * 16));
                MMAF16(acc[mt][0], a0, a1, a2, a3, bf[0], bf[1]);
                MMAF16(acc[mt][1], a0, a1, a2, a3, bf[2], bf[3]);
                MMAF16(acc[mt][2], a0, a1, a2, a3, bf[4], bf[5]);
                MMAF16(acc[mt][3], a0, a1, a2, a3, bf[6], bf[7]);
            }
        }
        __syncwarp();
        if (lid == 0) MBAR_ARRIVE(sb + EMPTY_OFF + (i % STG) * 8);
    }

    // epilogue: direct float2 stores
#pragma unroll
    for (int mt = 0; mt < 2; mt++) {
#pragma unroll
        for (int nt = 0; nt < 4; nt++) {
            int m = m0 + wm * 32 + mt * 16 + (lid >> 2);
            int n = n0 + wn * 32 + nt * 8 + ((lid & 3) << 1);
            int b2 = n / NPB, p2 = n - b2 * NPB;
            float* o = out + ((size_t)b2 * COUT + m) * NPB + p2;
            *(float2*)o = make_float2(acc[mt][nt][0], acc[mt][nt][1]);
            *(float2*)(o + 8 * NPB) = make_float2(acc[mt][nt][2], acc[mt][nt][3]);
        }
    }
}

// ============================================================================
extern "C" void kernel_launch(void* const* d_in, const int* in_sizes, int n_in,
                              void* d_out, int out_size) {
    const float* x  = (const float*)d_in[0];
    const float* gw = (const float*)d_in[1];
    const float* gb = (const float*)d_in[2];
    const float* gm = (const float*)d_in[3];
    const float* gv = (const float*)d_in[4];
    const float* cw = (const float*)d_in[5];
    float* out = (float*)d_out;

    cudaFuncSetAttribute(gemm_mma, cudaFuncAttributeMaxDynamicSharedMemorySize, SMEM_TOT);

    fuse_pool<<<dim3(NBLK, 9), 256>>>(x, gw, gb, gm, gv, cw);
    gemm_mma<<<dim3(NBLK, 2), 256, SMEM_TOT>>>(out);
}